// round 17
// baseline (speedup 1.0000x reference)
#include <cuda_runtime.h>
#include <cstdint>

#define THREADS 512

// Packed fp32x2 FMA (Blackwell FFMA2) — only reachable via PTX.
static __device__ __forceinline__ void fma2(unsigned long long& d,
                                            unsigned long long a,
                                            unsigned long long b) {
    asm("fma.rn.f32x2 %0, %1, %2, %0;" : "+l"(d) : "l"(a), "l"(b));
}

static __device__ __forceinline__ float unpack_sum(unsigned long long A) {
    return __uint_as_float((unsigned)A) + __uint_as_float((unsigned)(A >> 32));
}

// Swizzled index into a 64x256 token-major tile: element (t, c) lives at
//   t*256 + ((((c>>2) ^ ((t>>3)&7)) << 2) | (c&3))
// -> rows spaced 8 tokens hit distinct bank-quads for 16B vector loads.
static __device__ __forceinline__ int swz_x(int t, int c) {
    return t * 256 + ((((c >> 2) ^ ((t >> 3) & 7)) << 2) | (c & 3));
}

// smem layout (floats):
//  sx : [0,      16384)  input window / out-proj result (swizzled 64x256)
//  so : [16384,  32768)  attention output / LN result   (swizzled 64x256)
//  wsm: [32768,  49152)  weight staging region (64KB; double buffers)
//  sq : [49152,  51456)  64x36
//  sk : [51456,  53760)  64x36
//  sv : [53760,  56064)  64x36
//  sP = sq (aliased, stride 68; 4352 <= 4608 floats of sq+sk)
// total 56064 floats = 224256 bytes

__global__ __launch_bounds__(THREADS, 1)
void lab_fused_kernel(const float* __restrict__ x,
                      const float* __restrict__ w_in,
                      const float* __restrict__ b_in,
                      const float* __restrict__ w_out,
                      const float* __restrict__ b_out,
                      const float* __restrict__ gamma,
                      const float* __restrict__ beta,
                      float* __restrict__ out)
{
    const float SCALE = 0.17677669529663687f;   // 1/sqrt(32)

    extern __shared__ float sm[];
    float* sx  = sm;
    float* so  = sm + 16384;
    float* wsm = sm + 32768;
    float* sq  = sm + 49152;
    float* sk  = sm + 51456;
    float* sv  = sm + 53760;
    float* sP  = sq;                 // stride 68, aliases sq||sk

    const int tid = threadIdx.x;
    const int n   = blockIdx.x;
    const int bb  = n >> 10;
    const int hn  = (n >> 5) & 31;
    const int wn  = n & 31;

    // ---------------- gather x window + stage QKV tile 0 ----------------
    const float* xw = x + (size_t)bb * 256 * 65536 + (size_t)(hn * 8) * 256 + wn * 8;
    for (int idx = tid; idx < 16384; idx += THREADS) {
        int c = idx >> 6, t = idx & 63;
        sx[swz_x(t, c)] = xw[(size_t)c * 65536 + (t >> 3) * 256 + (t & 7)];
    }
    #pragma unroll
    for (int l = 0; l < 12; ++l) {
        int idx = tid + l * THREADS;
        int r = idx >> 6, kc = idx & 63;
        int e = (r < 32) ? r : (r < 64) ? (256 + r - 32) : (512 + r - 64);   // h=0
        wsm[r * 64 + ((((kc >> 2) ^ (r & 15)) << 2) | (kc & 3))] = w_in[e * 256 + kc];
    }
    __syncthreads();

    const int w    = tid >> 5;
    const int lane = tid & 31;

    // QKV mapping: warp w -> cols [6w, 6w+6); lane = tgq*2 + cgq
    const int tgq  = lane >> 1;          // 0..15, 4 tokens each
    const int cgq  = lane & 1;           // 0..1, 3 cols each
    const int tok0 = tgq * 4;
    const int colq = w * 6 + cgq * 3;
    const int xorA = (tok0 >> 3) & 7;    // same for tok0..tok0+3

    // scores/PV mapping
    const int ty = tid >> 4;             // 0..31, rows {2ty, 2ty+1}
    const int tx = tid & 15;

    // out-proj mapping: warp w -> 8 cols; lane = tgo*4 + cgo
    const int tgo  = lane >> 2;          // 0..7, 8 tokens each
    const int cgo  = lane & 3;           // 0..3, 2 cols each
    const int toko = tgo * 8;

    // ---------------- per head: QKV GEMM + attention ----------------
    for (int h = 0; h < 8; ++h) {
        unsigned long long acc[4][3];
        #pragma unroll
        for (int i = 0; i < 4; ++i)
            #pragma unroll
            for (int j = 0; j < 3; ++j) acc[i][j] = 0ull;

        for (int kt = 0; kt < 4; ++kt) {
            const int s  = h * 4 + kt;
            const int sn = s + 1;
            float pf[12];
            if (sn < 32) {
                const int h2  = sn >> 2;
                const int kb2 = (sn & 3) << 6;
                #pragma unroll
                for (int l = 0; l < 12; ++l) {
                    int idx = tid + l * THREADS;
                    int r = idx >> 6, kc = idx & 63;
                    int e = (r < 32) ? (h2 * 32 + r)
                          : (r < 64) ? (256 + h2 * 32 + r - 32)
                                     : (512 + h2 * 32 + r - 64);
                    pf[l] = w_in[e * 256 + kb2 + kc];
                }
            }
            const float* wb = wsm + (s & 1) * 6144;
            const int kb = kt << 6;
            #pragma unroll 4
            for (int kk = 0; kk < 64; kk += 4) {
                const int ch = ((((kb + kk) >> 2) ^ xorA) << 2);
                ulonglong2 a[4];
                #pragma unroll
                for (int i = 0; i < 4; ++i)
                    a[i] = *(const ulonglong2*)(sx + (tok0 + i) * 256 + ch);
                ulonglong2 bv[3];
                #pragma unroll
                for (int j = 0; j < 3; ++j) {
                    const int r = colq + j;
                    bv[j] = *(const ulonglong2*)(wb + r * 64 + (((kk >> 2) ^ (r & 15)) << 2));
                }
                #pragma unroll
                for (int i = 0; i < 4; ++i) {
                    #pragma unroll
                    for (int j = 0; j < 3; ++j) {
                        fma2(acc[i][j], a[i].x, bv[j].x);
                        fma2(acc[i][j], a[i].y, bv[j].y);
                    }
                }
            }
            if (sn < 32) {
                float* wnb = wsm + (sn & 1) * 6144;
                #pragma unroll
                for (int l = 0; l < 12; ++l) {
                    int idx = tid + l * THREADS;
                    int r = idx >> 6, kc = idx & 63;
                    wnb[r * 64 + ((((kc >> 2) ^ (r & 15)) << 2) | (kc & 3))] = pf[l];
                }
            }
            __syncthreads();
        }

        // epilogue: reduce packed pairs, add bias, scatter to q/k/v
        #pragma unroll
        for (int j = 0; j < 3; ++j) {
            const int col = colq + j;
            float* dst; int d, e;
            if (col < 32)      { dst = sq; d = col;      e = h * 32 + d; }
            else if (col < 64) { dst = sk; d = col - 32; e = 256 + h * 32 + d; }
            else               { dst = sv; d = col - 64; e = 512 + h * 32 + d; }
            const float bias = b_in[e];
            #pragma unroll
            for (int i = 0; i < 4; ++i)
                dst[(tok0 + i) * 36 + d] = unpack_sum(acc[i][j]) + bias;
        }
        __syncthreads();

        // scores + softmax entirely in registers (rows 2ty, 2ty+1; cols tx+16j)
        float p[2][4];
        {
            float f[2][4];
            #pragma unroll
            for (int i = 0; i < 2; ++i)
                #pragma unroll
                for (int j = 0; j < 4; ++j) f[i][j] = 0.f;
            #pragma unroll 2
            for (int d4 = 0; d4 < 32; d4 += 4) {
                float4 q0 = *(const float4*)(sq + (2 * ty) * 36 + d4);
                float4 q1 = *(const float4*)(sq + (2 * ty + 1) * 36 + d4);
                #pragma unroll
                for (int j = 0; j < 4; ++j) {
                    float4 k4 = *(const float4*)(sk + (tx + 16 * j) * 36 + d4);
                    f[0][j] = fmaf(q0.x, k4.x, f[0][j]);
                    f[0][j] = fmaf(q0.y, k4.y, f[0][j]);
                    f[0][j] = fmaf(q0.z, k4.z, f[0][j]);
                    f[0][j] = fmaf(q0.w, k4.w, f[0][j]);
                    f[1][j] = fmaf(q1.x, k4.x, f[1][j]);
                    f[1][j] = fmaf(q1.y, k4.y, f[1][j]);
                    f[1][j] = fmaf(q1.z, k4.z, f[1][j]);
                    f[1][j] = fmaf(q1.w, k4.w, f[1][j]);
                }
            }
            #pragma unroll
            for (int i = 0; i < 2; ++i) {
                float m = fmaxf(fmaxf(f[i][0], f[i][1]), fmaxf(f[i][2], f[i][3]));
                #pragma unroll
                for (int o = 8; o > 0; o >>= 1)
                    m = fmaxf(m, __shfl_xor_sync(0xffffffffu, m, o));
                float s = 0.f;
                #pragma unroll
                for (int j = 0; j < 4; ++j) {
                    p[i][j] = __expf((f[i][j] - m) * SCALE);
                    s += p[i][j];
                }
                #pragma unroll
                for (int o = 8; o > 0; o >>= 1)
                    s += __shfl_xor_sync(0xffffffffu, s, o);
                const float inv = 1.0f / s;
                #pragma unroll
                for (int j = 0; j < 4; ++j) p[i][j] *= inv;
            }
        }
        __syncthreads();   // all reads of sq/sk finished before sP overwrite
        #pragma unroll
        for (int i = 0; i < 2; ++i)
            #pragma unroll
            for (int j = 0; j < 4; ++j)
                sP[(2 * ty + i) * 68 + tx + 16 * j] = p[i][j];
        __syncthreads();

        // o_h = P @ V -> so[:, h*32 : h*32+32]
        {
            float o00 = 0.f, o01 = 0.f, o10 = 0.f, o11 = 0.f;
            #pragma unroll 2
            for (int k4 = 0; k4 < 64; k4 += 4) {
                float4 p0 = *(const float4*)(sP + (2 * ty) * 68 + k4);
                float4 p1 = *(const float4*)(sP + (2 * ty + 1) * 68 + k4);
                float pa[4] = {p0.x, p0.y, p0.z, p0.w};
                float pb[4] = {p1.x, p1.y, p1.z, p1.w};
                #pragma unroll
                for (int dk = 0; dk < 4; ++dk) {
                    const float v0 = sv[(k4 + dk) * 36 + tx];
                    const float v1 = sv[(k4 + dk) * 36 + tx + 16];
                    o00 = fmaf(pa[dk], v0, o00);
                    o01 = fmaf(pa[dk], v1, o01);
                    o10 = fmaf(pb[dk], v0, o10);
                    o11 = fmaf(pb[dk], v1, o11);
                }
            }
            const int t0 = 2 * ty, t1 = t0 + 1;
            const int c0 = h * 32 + tx, c1 = c0 + 16;
            so[swz_x(t0, c0)] = o00;
            so[swz_x(t0, c1)] = o01;
            so[swz_x(t1, c0)] = o10;
            so[swz_x(t1, c1)] = o11;
        }
        __syncthreads();
    }

    // ---------------- out projection: sx = so @ w_out^T + b_out ----------------
    // stage OP tile g=0 (half 0, 128 rows x 32 k, row stride 32, ^(r&7) swizzle)
    #pragma unroll
    for (int l = 0; l < 8; ++l) {
        int idx = tid + l * THREADS;
        int r = idx >> 5, kc = idx & 31;
        wsm[r * 32 + ((((kc >> 2) ^ (r & 7)) << 2) | (kc & 3))] = w_out[r * 256 + kc];
    }
    __syncthreads();

    for (int half = 0; half < 2; ++half) {
        const int co0 = half << 7;
        unsigned long long acc2[8][2];
        #pragma unroll
        for (int i = 0; i < 8; ++i) { acc2[i][0] = 0ull; acc2[i][1] = 0ull; }

        for (int s2 = 0; s2 < 8; ++s2) {
            const int g  = half * 8 + s2;
            const int kb = s2 << 5;
            float pf2[8];
            if (g + 1 < 16) {
                const int co0n = ((g + 1) >> 3) << 7;
                const int kbn  = ((g + 1) & 7) << 5;
                #pragma unroll
                for (int l = 0; l < 8; ++l) {
                    int idx = tid + l * THREADS;
                    int r = idx >> 5, kc = idx & 31;
                    pf2[l] = w_out[(co0n + r) * 256 + kbn + kc];
                }
            }
            const float* ob = wsm + (g & 1) * 4096;
            #pragma unroll 4
            for (int kk = 0; kk < 32; kk += 4) {
                const int ch = ((((kb + kk) >> 2) ^ tgo) << 2);
                ulonglong2 a[8];
                #pragma unroll
                for (int i = 0; i < 8; ++i)
                    a[i] = *(const ulonglong2*)(so + (toko + i) * 256 + ch);
                ulonglong2 bv[2];
                #pragma unroll
                for (int j = 0; j < 2; ++j) {
                    const int r = w * 8 + cgo * 2 + j;
                    bv[j] = *(const ulonglong2*)(ob + r * 32 + (((kk >> 2) ^ (r & 7)) << 2));
                }
                #pragma unroll
                for (int i = 0; i < 8; ++i) {
                    #pragma unroll
                    for (int j = 0; j < 2; ++j) {
                        fma2(acc2[i][j], a[i].x, bv[j].x);
                        fma2(acc2[i][j], a[i].y, bv[j].y);
                    }
                }
            }
            if (g + 1 < 16) {
                float* obn = wsm + ((g + 1) & 1) * 4096;
                #pragma unroll
                for (int l = 0; l < 8; ++l) {
                    int idx = tid + l * THREADS;
                    int r = idx >> 5, kc = idx & 31;
                    obn[r * 32 + ((((kc >> 2) ^ (r & 7)) << 2) | (kc & 3))] = pf2[l];
                }
            }
            __syncthreads();
        }

        #pragma unroll
        for (int j = 0; j < 2; ++j) {
            const int col = co0 + w * 8 + cgo * 2 + j;
            const float bias = b_out[col];
            #pragma unroll
            for (int i = 0; i < 8; ++i)
                sx[swz_x(toko + i, col)] = unpack_sum(acc2[i][j]) + bias;
        }
    }
    __syncthreads();

    // ---------------- LayerNorm over channels (per token) ----------------
    {
        const int wid = tid >> 5;
        for (int r = 0; r < 4; ++r) {
            const int t  = wid * 4 + r;
            const int xo = (t >> 3) & 7;
            float v[8];
            #pragma unroll
            for (int j = 0; j < 8; ++j) {
                const int c = j * 32 + lane;
                v[j] = sx[t * 256 + ((((c >> 2) ^ xo) << 2) | (c & 3))];
            }
            float s = 0.f;
            #pragma unroll
            for (int j = 0; j < 8; ++j) s += v[j];
            #pragma unroll
            for (int o = 16; o > 0; o >>= 1) s += __shfl_xor_sync(0xffffffffu, s, o);
            const float mu = s * (1.0f / 256.0f);
            float q2 = 0.f;
            #pragma unroll
            for (int j = 0; j < 8; ++j) { float d = v[j] - mu; q2 = fmaf(d, d, q2); }
            #pragma unroll
            for (int o = 16; o > 0; o >>= 1) q2 += __shfl_xor_sync(0xffffffffu, q2, o);
            const float rs = rsqrtf(q2 * (1.0f / 256.0f) + 1e-5f);
            #pragma unroll
            for (int j = 0; j < 8; ++j) {
                const int c = j * 32 + lane;
                so[t * 256 + ((((c >> 2) ^ xo) << 2) | (c & 3))] =
                    (v[j] - mu) * rs * gamma[c] + beta[c];
            }
        }
    }
    __syncthreads();

    // ---------------- scatter to NCHW output ----------------
    float* ow = out + (size_t)bb * 256 * 65536 + (size_t)(hn * 8) * 256 + wn * 8;
    for (int idx = tid; idx < 16384; idx += THREADS) {
        int c = idx >> 6, t = idx & 63;
        ow[(size_t)c * 65536 + (t >> 3) * 256 + (t & 7)] = so[swz_x(t, c)];
    }
}

extern "C" void kernel_launch(void* const* d_in, const int* in_sizes, int n_in,
                              void* d_out, int out_size) {
    (void)in_sizes; (void)n_in; (void)out_size;
    const float* x     = (const float*)d_in[0];
    const float* w_in  = (const float*)d_in[1];
    const float* b_in  = (const float*)d_in[2];
    const float* w_out = (const float*)d_in[3];
    const float* b_out = (const float*)d_in[4];
    const float* gamma = (const float*)d_in[5];
    const float* beta  = (const float*)d_in[6];
    float* out = (float*)d_out;

    const int smem_bytes = 56064 * 4;   // 224256 B
    cudaFuncSetAttribute(lab_fused_kernel,
                         cudaFuncAttributeMaxDynamicSharedMemorySize, smem_bytes);
    lab_fused_kernel<<<4096, THREADS, smem_bytes>>>(x, w_in, b_in, w_out, b_out,
                                                    gamma, beta, out);
}